// round 3
// baseline (speedup 1.0000x reference)
#include <cuda_runtime.h>
#include <cuda_bf16.h>
#include <cstdint>
#include <cstddef>

// ---------------------------------------------------------------------------
// AAM-softmax loss, sm_100-safe (no tcgen05 / no 'a'-suffix PTX features).
//   x[1024,256] f32, weight[100000,256] f32, label[1024] (i64 or i32) -> f32 loss
//
//   1) prep_kernel:   g_xn = normalize(x) (exact), g_xr = tf32-rounded copy
//   2) rnorm_kernel:  g_rnorm[c] = 1/max(||w_c||,1e-12), g_wr = tf32-rounded w
//   3) gemm_kernel:   mma.sync tf32 128x256 tiles, fused exp-sum epilogue
//   4) finalize_kernel: row totals + exact fp32 target dot + margin fixup
//   5) reduce_kernel: mean -> d_out[0]
// ---------------------------------------------------------------------------

#define B_ROWS 1024
#define DDIM   256
#define CCLS   100000
#define BM 128
#define BN 256
#define BK 32
#define NKS 8                    // 256 / 32
#define NTN 391                  // ceil(100000/256)
#define STAGE 49152              // A 16KB + B 32KB
#define SA_OFF 0
#define SB_OFF 16384
#define SMEM_TOTAL (3 * STAGE)   // 147456

#define K_COS_M 0.9950041652780258f
#define K_SIN_M 0.09983341664682815f
#define K_TH   (-0.9950041652780258f)
#define K_MM    0.009983341664682815f

__device__ float g_xn[B_ROWS * DDIM];             // exact normalized x
__device__ float g_xr[B_ROWS * DDIM];             // tf32-rounded normalized x
__device__ float g_wr[(size_t)CCLS * DDIM];       // tf32-rounded weights
__device__ float g_rnorm[CCLS];
__device__ float g_part[(size_t)B_ROWS * NTN];
__device__ float g_lossb[B_ROWS];

// ---------------------------------------------------------------------------
__device__ __forceinline__ uint32_t smem_u32(const void* p) {
    uint32_t a;
    asm("{ .reg .u64 t; cvta.to.shared.u64 t, %1; cvt.u32.u64 %0, t; }"
        : "=r"(a) : "l"(p));
    return a;
}

__device__ __forceinline__ float tf32_round(float v) {
    uint32_t o;
    asm("cvt.rna.tf32.f32 %0, %1;" : "=r"(o) : "f"(v));
    return __uint_as_float(o);
}

#define CP_ASYNC16(sm, g) \
    asm volatile("cp.async.cg.shared.global [%0], [%1], 16;" :: "r"(sm), "l"(g))
#define CP_COMMIT() asm volatile("cp.async.commit_group;" ::: "memory")

#define LDSM_X4(r0, r1, r2, r3, addr) \
    asm volatile("ldmatrix.sync.aligned.m8n8.x4.shared.b16 {%0,%1,%2,%3}, [%4];" \
                 : "=r"(r0), "=r"(r1), "=r"(r2), "=r"(r3) : "r"(addr))

#define MMA_TF32(c, a, b0, b1) \
    asm volatile("mma.sync.aligned.m16n8k8.row.col.f32.tf32.tf32.f32 " \
                 "{%0,%1,%2,%3}, {%4,%5,%6,%7}, {%8,%9}, {%0,%1,%2,%3};" \
                 : "+f"((c)[0]), "+f"((c)[1]), "+f"((c)[2]), "+f"((c)[3]) \
                 : "r"((a)[0]), "r"((a)[1]), "r"((a)[2]), "r"((a)[3]), \
                   "r"(b0), "r"(b1))

// ---------------------------------------------------------------------------
// Kernel 1: normalize x rows; write exact + tf32-rounded copies
// ---------------------------------------------------------------------------
__global__ void __launch_bounds__(256) prep_kernel(const float* __restrict__ x) {
    int gw = (blockIdx.x * blockDim.x + threadIdx.x) >> 5;
    int lane = threadIdx.x & 31;
    if (gw >= B_ROWS) return;
    const float4* xv = (const float4*)(x + (size_t)gw * DDIM);
    float4 a0 = xv[lane * 2], a1 = xv[lane * 2 + 1];
    float ss = a0.x*a0.x + a0.y*a0.y + a0.z*a0.z + a0.w*a0.w
             + a1.x*a1.x + a1.y*a1.y + a1.z*a1.z + a1.w*a1.w;
    #pragma unroll
    for (int o = 16; o; o >>= 1) ss += __shfl_xor_sync(0xffffffffu, ss, o);
    float inv = 1.f / fmaxf(sqrtf(ss), 1e-12f);
    a0.x *= inv; a0.y *= inv; a0.z *= inv; a0.w *= inv;
    a1.x *= inv; a1.y *= inv; a1.z *= inv; a1.w *= inv;
    ((float4*)(g_xn + (size_t)gw * DDIM))[lane * 2]     = a0;
    ((float4*)(g_xn + (size_t)gw * DDIM))[lane * 2 + 1] = a1;
    float4 r0, r1;
    r0.x = tf32_round(a0.x); r0.y = tf32_round(a0.y);
    r0.z = tf32_round(a0.z); r0.w = tf32_round(a0.w);
    r1.x = tf32_round(a1.x); r1.y = tf32_round(a1.y);
    r1.z = tf32_round(a1.z); r1.w = tf32_round(a1.w);
    ((float4*)(g_xr + (size_t)gw * DDIM))[lane * 2]     = r0;
    ((float4*)(g_xr + (size_t)gw * DDIM))[lane * 2 + 1] = r1;
}

// ---------------------------------------------------------------------------
// Kernel 2: weight inverse norms + tf32-rounded weight copy
// ---------------------------------------------------------------------------
__global__ void __launch_bounds__(256) rnorm_kernel(const float* __restrict__ wt) {
    int gw = (blockIdx.x * blockDim.x + threadIdx.x) >> 5;
    int lane = threadIdx.x & 31;
    if (gw >= CCLS) return;
    const float4* wv = (const float4*)(wt + (size_t)gw * DDIM);
    float4 a0 = wv[lane * 2], a1 = wv[lane * 2 + 1];
    float ss = a0.x*a0.x + a0.y*a0.y + a0.z*a0.z + a0.w*a0.w
             + a1.x*a1.x + a1.y*a1.y + a1.z*a1.z + a1.w*a1.w;
    #pragma unroll
    for (int o = 16; o; o >>= 1) ss += __shfl_xor_sync(0xffffffffu, ss, o);
    if (lane == 0) g_rnorm[gw] = 1.f / fmaxf(sqrtf(ss), 1e-12f);
    float4 r0, r1;
    r0.x = tf32_round(a0.x); r0.y = tf32_round(a0.y);
    r0.z = tf32_round(a0.z); r0.w = tf32_round(a0.w);
    r1.x = tf32_round(a1.x); r1.y = tf32_round(a1.y);
    r1.z = tf32_round(a1.z); r1.w = tf32_round(a1.w);
    ((float4*)(g_wr + (size_t)gw * DDIM))[lane * 2]     = r0;
    ((float4*)(g_wr + (size_t)gw * DDIM))[lane * 2 + 1] = r1;
}

// ---------------------------------------------------------------------------
// Kernel 3: tf32 mma.sync GEMM + fused exp-sum epilogue
//   grid = (391, 8): x = 256-class tile, y = 128-row tile.
//   8 warps as 2x4 grid of 64x64 warp tiles. 3-stage cp.async pipeline.
// ---------------------------------------------------------------------------
__global__ void __launch_bounds__(256, 1) gemm_kernel() {
    extern __shared__ __align__(1024) char smem[];
    const uint32_t sb = smem_u32(smem);
    const int tid = threadIdx.x;
    const int wid = tid >> 5, lane = tid & 31;
    const int wr = wid >> 2, wc = wid & 3;   // warp row (0..1), col (0..3)
    const int tn = blockIdx.x, tm = blockIdx.y;
    const int climit = CCLS - tn * BN;       // valid classes in this tile

    // ldmatrix address pre-computation
    const int lr = lane & 7, lg = lane >> 3;
    const int ac4 = lg >> 1;                 // A k-chunk bit
    const int bc4 = lg & 1;                  // B k-chunk bit
    uint32_t aoff[4]; int amask[4];
    uint32_t boff[4]; int bmask[4];
    #pragma unroll
    for (int mt = 0; mt < 4; mt++) {
        int ar = wr * 64 + mt * 16 + (lg & 1) * 8 + lr;
        aoff[mt] = (uint32_t)ar * 128; amask[mt] = ar & 7;
    }
    #pragma unroll
    for (int p = 0; p < 4; p++) {
        int br = wc * 64 + p * 16 + (lg >> 1) * 8 + lr;
        boff[p] = (uint32_t)br * 128; bmask[p] = br & 7;
    }

    float acc[4][8][4];
    #pragma unroll
    for (int mt = 0; mt < 4; mt++)
        #pragma unroll
        for (int nt = 0; nt < 8; nt++)
            #pragma unroll
            for (int r = 0; r < 4; r++) acc[mt][nt][r] = 0.f;

    const float* abase = g_xr + (size_t)(tm * BM) * DDIM;
    const float* bbase = g_wr + (size_t)(tn * BN) * DDIM;

    auto load_stage = [&](int kk, int stg) {
        uint32_t st = sb + (uint32_t)stg * STAGE;
        #pragma unroll
        for (int i = 0; i < 4; i++) {
            int u = i * 256 + tid;
            int r = u >> 3, c4 = u & 7;
            uint32_t so = st + SA_OFF + (uint32_t)r * 128 + (uint32_t)((c4 ^ (r & 7)) << 4);
            CP_ASYNC16(so, abase + (size_t)r * DDIM + kk * BK + c4 * 4);
        }
        #pragma unroll
        for (int i = 0; i < 8; i++) {
            int u = i * 256 + tid;
            int r = u >> 3, c4 = u & 7;
            if (r < climit) {
                uint32_t so = st + SB_OFF + (uint32_t)r * 128 + (uint32_t)((c4 ^ (r & 7)) << 4);
                CP_ASYNC16(so, bbase + (size_t)r * DDIM + kk * BK + c4 * 4);
            }
        }
    };

    load_stage(0, 0); CP_COMMIT();
    load_stage(1, 1); CP_COMMIT();
    load_stage(2, 2); CP_COMMIT();

    #pragma unroll
    for (int k = 0; k < NKS; k++) {
        if (k <= 5)      asm volatile("cp.async.wait_group 2;" ::: "memory");
        else if (k == 6) asm volatile("cp.async.wait_group 1;" ::: "memory");
        else             asm volatile("cp.async.wait_group 0;" ::: "memory");
        __syncthreads();

        const uint32_t stb = sb + (uint32_t)(k % 3) * STAGE;
        #pragma unroll
        for (int ks = 0; ks < 4; ks++) {
            uint32_t af[4][4];
            #pragma unroll
            for (int mt = 0; mt < 4; mt++) {
                uint32_t ad = stb + SA_OFF + aoff[mt]
                            + (uint32_t)(((ks * 2 + ac4) ^ amask[mt]) << 4);
                LDSM_X4(af[mt][0], af[mt][1], af[mt][2], af[mt][3], ad);
            }
            uint32_t bf[4][4];
            #pragma unroll
            for (int p = 0; p < 4; p++) {
                uint32_t bd = stb + SB_OFF + boff[p]
                            + (uint32_t)(((ks * 2 + bc4) ^ bmask[p]) << 4);
                LDSM_X4(bf[p][0], bf[p][1], bf[p][2], bf[p][3], bd);
            }
            #pragma unroll
            for (int mt = 0; mt < 4; mt++)
                #pragma unroll
                for (int nt = 0; nt < 8; nt++) {
                    int p = nt >> 1;
                    if (nt & 1) MMA_TF32(acc[mt][nt], af[mt], bf[p][2], bf[p][3]);
                    else        MMA_TF32(acc[mt][nt], af[mt], bf[p][0], bf[p][1]);
                }
        }
        __syncthreads();
        if (k < NKS - 3) { load_stage(k + 3, k % 3); CP_COMMIT(); }
    }

    // ---- epilogue: scale by 1/||w||, exp(50c-50), per-row partial sums ----
    float* rp  = (float*)smem;                 // [128][4] warp-col partials
    float* srn = (float*)(smem + 2048);        // [256] rnorm tile
    if (tid < BN) {
        int cls = tn * BN + tid;
        srn[tid] = (cls < CCLS) ? g_rnorm[cls] : 0.f;
    }
    __syncthreads();

    int vmax = climit < BN ? climit : BN;
    float rs[4][2];
    #pragma unroll
    for (int mt = 0; mt < 4; mt++) {
        #pragma unroll
        for (int h = 0; h < 2; h++) {
            float s = 0.f;
            #pragma unroll
            for (int nt = 0; nt < 8; nt++) {
                int n0 = wc * 64 + nt * 8 + (lane & 3) * 2;
                float v0 = acc[mt][nt][h * 2]     * srn[n0];
                float v1 = acc[mt][nt][h * 2 + 1] * srn[n0 + 1];
                float e0 = __expf(fmaf(50.f, v0, -50.f));
                float e1 = __expf(fmaf(50.f, v1, -50.f));
                s += (n0     < vmax ? e0 : 0.f);
                s += (n0 + 1 < vmax ? e1 : 0.f);
            }
            s += __shfl_xor_sync(0xffffffffu, s, 1);
            s += __shfl_xor_sync(0xffffffffu, s, 2);
            rs[mt][h] = s;
        }
    }
    if ((lane & 3) == 0) {
        #pragma unroll
        for (int mt = 0; mt < 4; mt++)
            #pragma unroll
            for (int h = 0; h < 2; h++) {
                int rl = wr * 64 + mt * 16 + h * 8 + (lane >> 2);
                rp[rl * 4 + wc] = rs[mt][h];
            }
    }
    __syncthreads();
    if (tid < BM) {
        float t = rp[tid * 4] + rp[tid * 4 + 1] + rp[tid * 4 + 2] + rp[tid * 4 + 3];
        g_part[(size_t)(tm * BM + tid) * NTN + tn] = t;
    }
}

// ---------------------------------------------------------------------------
// Kernel 4: per-row loss (sum partials, exact fp32 target dot, phi fixup)
// ---------------------------------------------------------------------------
__global__ void __launch_bounds__(256) finalize_kernel(const float* __restrict__ wt,
                                                       const void* __restrict__ lab) {
    __shared__ int s_is64;
    int tid = threadIdx.x, wid = tid >> 5, lane = tid & 31;
    if (wid == 0) {
        const int* L = (const int*)lab;
        unsigned b = __ballot_sync(0xffffffffu, L[2 * lane + 1] == 0);
        if (lane == 0) s_is64 = (b == 0xffffffffu) ? 1 : 0;
    }
    __syncthreads();
    int row = blockIdx.x * 8 + wid;
    int cls = s_is64 ? (int)((const long long*)lab)[row]
                     : ((const int*)lab)[row];

    float s = 0.f;
    const float* pr = g_part + (size_t)row * NTN;
    for (int i = lane; i < NTN; i += 32) s += pr[i];

    const float4* xr = (const float4*)(g_xn + (size_t)row * DDIM);
    const float4* wrp = (const float4*)(wt + (size_t)cls * DDIM);
    float4 x0 = xr[lane * 2], x1 = xr[lane * 2 + 1];
    float4 w0 = wrp[lane * 2], w1 = wrp[lane * 2 + 1];
    float d = x0.x*w0.x + x0.y*w0.y + x0.z*w0.z + x0.w*w0.w
            + x1.x*w1.x + x1.y*w1.y + x1.z*w1.z + x1.w*w1.w;
    #pragma unroll
    for (int o = 16; o; o >>= 1) {
        s += __shfl_xor_sync(0xffffffffu, s, o);
        d += __shfl_xor_sync(0xffffffffu, d, o);
    }
    if (lane == 0) {
        float cosv = d * g_rnorm[cls];
        float sine = sqrtf(fminf(fmaxf(1.f - cosv * cosv, 0.f), 1.f));
        float phi = cosv * K_COS_M - sine * K_SIN_M;
        if (!(cosv - K_TH > 0.f)) phi = cosv - K_MM;
        // replace the (tf32-noisy) target term with the exact phi term
        float S = s - expf(50.f * cosv - 50.f) + expf(50.f * phi - 50.f);
        g_lossb[row] = (logf(S) + 50.f) - 50.f * phi;   // logz - target_logit
    }
}

// ---------------------------------------------------------------------------
// Kernel 5: mean over 1024 rows
// ---------------------------------------------------------------------------
__global__ void __launch_bounds__(512) reduce_kernel(float* __restrict__ out) {
    __shared__ float sm[16];
    int tid = threadIdx.x, wid = tid >> 5, lane = tid & 31;
    float v = g_lossb[tid] + g_lossb[tid + 512];
    #pragma unroll
    for (int o = 16; o; o >>= 1) v += __shfl_xor_sync(0xffffffffu, v, o);
    if (lane == 0) sm[wid] = v;
    __syncthreads();
    if (wid == 0) {
        float t = (lane < 16) ? sm[lane] : 0.f;
        #pragma unroll
        for (int o = 8; o; o >>= 1) t += __shfl_xor_sync(0xffffffffu, t, o);
        if (lane == 0) out[0] = t * (1.f / (float)B_ROWS);
    }
}

// ---------------------------------------------------------------------------
extern "C" void kernel_launch(void* const* d_in, const int* in_sizes, int n_in,
                              void* d_out, int out_size) {
    const float* x  = (const float*)d_in[0];
    const float* wt = (const float*)d_in[1];
    const void*  lb = d_in[2];
    float* out = (float*)d_out;

    cudaFuncSetAttribute(gemm_kernel, cudaFuncAttributeMaxDynamicSharedMemorySize,
                         SMEM_TOTAL);

    prep_kernel<<<B_ROWS / 8, 256>>>(x);
    rnorm_kernel<<<CCLS / 8, 256>>>(wt);
    gemm_kernel<<<dim3(NTN, 8), 256, SMEM_TOTAL>>>();
    finalize_kernel<<<B_ROWS / 8, 256>>>(wt, lb);
    reduce_kernel<<<1, 512>>>(out);
}

// round 4
// speedup vs baseline: 1.6078x; 1.6078x over previous
#include <cuda_runtime.h>
#include <cuda_bf16.h>
#include <cstdint>
#include <cstddef>

// ---------------------------------------------------------------------------
// AAM-softmax loss, sm_100-safe (plain-PTX subset: cp.async/ldmatrix/mma.sync).
//   x[1024,256] f32, weight[100000,256] f32, label[1024] (i64/i32) -> f32 loss
//
//   1) prep_kernel:  g_xn = normalize(x) fp32 (for exact target dot),
//                    g_xb = bf16(normalize(x))            (GEMM A)
//   2) wconv_kernel: g_wb = bf16(normalize(w))            (GEMM B)
//   3) gemm_kernel:  bf16 mma.sync 128x256xK256, fused exp(50c-50) row sums
//                    -> g_part[tile][row]  (transposed, coalesced)
//   4) rowsum_kernel: coalesced reduction over 391 tiles -> g_rowsum[row]
//   5) finalize_kernel: exact fp32 target dot + margin fixup -> g_lossb
//   6) reduce_kernel: mean -> d_out[0]
// ---------------------------------------------------------------------------

#define B_ROWS 1024
#define DDIM   256
#define CCLS   100000
#define BM 128
#define BN 256
#define BK 64
#define NKS 4                    // 256 / 64
#define NTN 391                  // ceil(100000/256)
#define STAGE 49152              // A 16KB + B 32KB
#define SA_OFF 0
#define SB_OFF 16384
#define SMEM_TOTAL (4 * STAGE)   // 196608 (all K prefetched)

#define K_COS_M 0.9950041652780258f
#define K_SIN_M 0.09983341664682815f
#define K_TH   (-0.9950041652780258f)
#define K_MM    0.009983341664682815f

__device__ float          g_xn[B_ROWS * DDIM];
__device__ __nv_bfloat16  g_xb[B_ROWS * DDIM];
__device__ __nv_bfloat16  g_wb[(size_t)CCLS * DDIM];
__device__ float          g_part[(size_t)NTN * B_ROWS];   // [tile][row]
__device__ float          g_rowsum[B_ROWS];
__device__ float          g_lossb[B_ROWS];

// ---------------------------------------------------------------------------
__device__ __forceinline__ uint32_t smem_u32(const void* p) {
    uint32_t a;
    asm("{ .reg .u64 t; cvta.to.shared.u64 t, %1; cvt.u32.u64 %0, t; }"
        : "=r"(a) : "l"(p));
    return a;
}

__device__ __forceinline__ uint32_t pack_bf2(float lo, float hi) {
    __nv_bfloat162 h = __float22bfloat162_rn(make_float2(lo, hi));
    return *reinterpret_cast<uint32_t*>(&h);
}

#define CP_ASYNC16(sm, g) \
    asm volatile("cp.async.cg.shared.global [%0], [%1], 16;" :: "r"(sm), "l"(g))
#define CP_COMMIT() asm volatile("cp.async.commit_group;" ::: "memory")

#define LDSM_X4(r0, r1, r2, r3, addr) \
    asm volatile("ldmatrix.sync.aligned.m8n8.x4.shared.b16 {%0,%1,%2,%3}, [%4];" \
                 : "=r"(r0), "=r"(r1), "=r"(r2), "=r"(r3) : "r"(addr))

#define MMA_BF16(c, a, b0, b1) \
    asm volatile("mma.sync.aligned.m16n8k16.row.col.f32.bf16.bf16.f32 " \
                 "{%0,%1,%2,%3}, {%4,%5,%6,%7}, {%8,%9}, {%0,%1,%2,%3};" \
                 : "+f"((c)[0]), "+f"((c)[1]), "+f"((c)[2]), "+f"((c)[3]) \
                 : "r"((a)[0]), "r"((a)[1]), "r"((a)[2]), "r"((a)[3]), \
                   "r"(b0), "r"(b1))

// ---------------------------------------------------------------------------
// Kernel 1: normalize x rows -> fp32 + bf16 copies
// ---------------------------------------------------------------------------
__global__ void __launch_bounds__(256) prep_kernel(const float* __restrict__ x) {
    int gw = (blockIdx.x * blockDim.x + threadIdx.x) >> 5;
    int lane = threadIdx.x & 31;
    if (gw >= B_ROWS) return;
    const float4* xv = (const float4*)(x + (size_t)gw * DDIM);
    float4 a0 = xv[lane * 2], a1 = xv[lane * 2 + 1];
    float ss = a0.x*a0.x + a0.y*a0.y + a0.z*a0.z + a0.w*a0.w
             + a1.x*a1.x + a1.y*a1.y + a1.z*a1.z + a1.w*a1.w;
    #pragma unroll
    for (int o = 16; o; o >>= 1) ss += __shfl_xor_sync(0xffffffffu, ss, o);
    float inv = 1.f / fmaxf(sqrtf(ss), 1e-12f);
    a0.x *= inv; a0.y *= inv; a0.z *= inv; a0.w *= inv;
    a1.x *= inv; a1.y *= inv; a1.z *= inv; a1.w *= inv;
    ((float4*)(g_xn + (size_t)gw * DDIM))[lane * 2]     = a0;
    ((float4*)(g_xn + (size_t)gw * DDIM))[lane * 2 + 1] = a1;
    uint4 pk;
    pk.x = pack_bf2(a0.x, a0.y); pk.y = pack_bf2(a0.z, a0.w);
    pk.z = pack_bf2(a1.x, a1.y); pk.w = pack_bf2(a1.z, a1.w);
    *(uint4*)(g_xb + (size_t)gw * DDIM + lane * 8) = pk;
}

// ---------------------------------------------------------------------------
// Kernel 2: normalized bf16 weights
// ---------------------------------------------------------------------------
__global__ void __launch_bounds__(256) wconv_kernel(const float* __restrict__ wt) {
    int gw = (blockIdx.x * blockDim.x + threadIdx.x) >> 5;
    int lane = threadIdx.x & 31;
    if (gw >= CCLS) return;
    const float4* wv = (const float4*)(wt + (size_t)gw * DDIM);
    float4 a0 = wv[lane * 2], a1 = wv[lane * 2 + 1];
    float ss = a0.x*a0.x + a0.y*a0.y + a0.z*a0.z + a0.w*a0.w
             + a1.x*a1.x + a1.y*a1.y + a1.z*a1.z + a1.w*a1.w;
    #pragma unroll
    for (int o = 16; o; o >>= 1) ss += __shfl_xor_sync(0xffffffffu, ss, o);
    float inv = 1.f / fmaxf(sqrtf(ss), 1e-12f);
    uint4 pk;
    pk.x = pack_bf2(a0.x * inv, a0.y * inv); pk.y = pack_bf2(a0.z * inv, a0.w * inv);
    pk.z = pack_bf2(a1.x * inv, a1.y * inv); pk.w = pack_bf2(a1.z * inv, a1.w * inv);
    *(uint4*)(g_wb + (size_t)gw * DDIM + lane * 8) = pk;
}

// ---------------------------------------------------------------------------
// Kernel 3: bf16 mma.sync GEMM + fused exp-sum epilogue
//   grid = (391, 8): x = 256-class tile, y = 128-row tile.
//   8 warps as 2x4 grid of 64x64 warp tiles. Full-K prefetch (4 stages).
// ---------------------------------------------------------------------------
__global__ void __launch_bounds__(256, 1) gemm_kernel() {
    extern __shared__ __align__(1024) char smem[];
    const uint32_t sb = smem_u32(smem);
    const int tid = threadIdx.x;
    const int wid = tid >> 5, lane = tid & 31;
    const int wr = wid >> 2, wc = wid & 3;   // warp row (0..1), col (0..3)
    const int tn = blockIdx.x, tm = blockIdx.y;
    const int climit = CCLS - tn * BN;

    const int lr = lane & 7, lg = lane >> 3;
    const int kb = lg >> 1;                  // k-half bit for ldmatrix groups
    const uint32_t arow = (uint32_t)(wr * 64 + (lg & 1) * 8 + lr) * 128;
    const uint32_t brow = (uint32_t)(wc * 64 + (lg & 1) * 8 + lr) * 128;

    float acc[4][8][4];
    #pragma unroll
    for (int mt = 0; mt < 4; mt++)
        #pragma unroll
        for (int nt = 0; nt < 8; nt++)
            #pragma unroll
            for (int r = 0; r < 4; r++) acc[mt][nt][r] = 0.f;

    const __nv_bfloat16* ab = g_xb + (size_t)(tm * BM) * DDIM;
    const __nv_bfloat16* bb = g_wb + (size_t)(tn * BN) * DDIM;

    auto load_stage = [&](int kk, int stg) {
        uint32_t st = sb + (uint32_t)stg * STAGE;
        #pragma unroll
        for (int i = 0; i < 4; i++) {
            int u = i * 256 + tid;
            int r = u >> 3, c8 = u & 7;
            uint32_t so = st + SA_OFF + (uint32_t)r * 128 + (uint32_t)((c8 ^ (r & 7)) << 4);
            CP_ASYNC16(so, ab + (size_t)r * DDIM + kk * BK + c8 * 8);
        }
        #pragma unroll
        for (int i = 0; i < 8; i++) {
            int u = i * 256 + tid;
            int r = u >> 3, c8 = u & 7;
            if (r < climit) {
                uint32_t so = st + SB_OFF + (uint32_t)r * 128 + (uint32_t)((c8 ^ (r & 7)) << 4);
                CP_ASYNC16(so, bb + (size_t)r * DDIM + kk * BK + c8 * 8);
            }
        }
    };

    load_stage(0, 0); CP_COMMIT();
    load_stage(1, 1); CP_COMMIT();
    load_stage(2, 2); CP_COMMIT();
    load_stage(3, 3); CP_COMMIT();

    #pragma unroll
    for (int k = 0; k < NKS; k++) {
        if (k == 0)      asm volatile("cp.async.wait_group 3;" ::: "memory");
        else if (k == 1) asm volatile("cp.async.wait_group 2;" ::: "memory");
        else if (k == 2) asm volatile("cp.async.wait_group 1;" ::: "memory");
        else             asm volatile("cp.async.wait_group 0;" ::: "memory");
        __syncthreads();

        const uint32_t stb = sb + (uint32_t)k * STAGE;
        const uint32_t abase = stb + SA_OFF + arow;
        const uint32_t bbase = stb + SB_OFF + brow;
        #pragma unroll
        for (int ks = 0; ks < 4; ks++) {
            const uint32_t cx = (uint32_t)(((ks * 2 + kb) ^ lr) << 4);
            uint32_t af[4][4];
            #pragma unroll
            for (int mt = 0; mt < 4; mt++)
                LDSM_X4(af[mt][0], af[mt][1], af[mt][2], af[mt][3],
                        abase + (uint32_t)mt * 2048 + cx);
            uint32_t bf[4][4];
            #pragma unroll
            for (int p = 0; p < 4; p++)
                LDSM_X4(bf[p][0], bf[p][1], bf[p][2], bf[p][3],
                        bbase + (uint32_t)p * 2048 + cx);
            // group mapping: r0=(n0-7,k0-7) r1=(n8-15,k0-7) r2=(n0-7,k8-15) r3=(n8-15,k8-15)
            #pragma unroll
            for (int mt = 0; mt < 4; mt++)
                #pragma unroll
                for (int nt = 0; nt < 8; nt++) {
                    int p = nt >> 1;
                    if (nt & 1) MMA_BF16(acc[mt][nt], af[mt], bf[p][1], bf[p][3]);
                    else        MMA_BF16(acc[mt][nt], af[mt], bf[p][0], bf[p][2]);
                }
        }
    }

    // ---- epilogue: exp(50c-50) row sums (weights pre-normalized) ----
    float* rp = (float*)smem;                // [128][4] warp-col partials
    int vmax = climit < BN ? climit : BN;
    #pragma unroll
    for (int mt = 0; mt < 4; mt++) {
        #pragma unroll
        for (int h = 0; h < 2; h++) {
            float s = 0.f;
            #pragma unroll
            for (int nt = 0; nt < 8; nt++) {
                int n0 = wc * 64 + nt * 8 + (lane & 3) * 2;
                float e0 = __expf(fmaf(50.f, acc[mt][nt][h * 2],     -50.f));
                float e1 = __expf(fmaf(50.f, acc[mt][nt][h * 2 + 1], -50.f));
                s += (n0     < vmax ? e0 : 0.f);
                s += (n0 + 1 < vmax ? e1 : 0.f);
            }
            s += __shfl_xor_sync(0xffffffffu, s, 1);
            s += __shfl_xor_sync(0xffffffffu, s, 2);
            if ((lane & 3) == 0)
                rp[(wr * 64 + mt * 16 + h * 8 + (lane >> 2)) * 4 + wc] = s;
        }
    }
    __syncthreads();
    if (tid < BM) {
        float t = (rp[tid * 4] + rp[tid * 4 + 1]) + (rp[tid * 4 + 2] + rp[tid * 4 + 3]);
        g_part[(size_t)tn * B_ROWS + tm * BM + tid] = t;   // coalesced, transposed
    }
}

// ---------------------------------------------------------------------------
// Kernel 4: coalesced row sums over 391 tiles
// ---------------------------------------------------------------------------
__global__ void __launch_bounds__(256) rowsum_kernel() {
    int row = blockIdx.x * 256 + threadIdx.x;
    float s0 = 0.f, s1 = 0.f, s2 = 0.f, s3 = 0.f;
    int i = 0;
    for (; i + 4 <= NTN; i += 4) {
        s0 += g_part[(size_t)(i + 0) * B_ROWS + row];
        s1 += g_part[(size_t)(i + 1) * B_ROWS + row];
        s2 += g_part[(size_t)(i + 2) * B_ROWS + row];
        s3 += g_part[(size_t)(i + 3) * B_ROWS + row];
    }
    for (; i < NTN; i++) s0 += g_part[(size_t)i * B_ROWS + row];
    g_rowsum[row] = (s0 + s1) + (s2 + s3);
}

// ---------------------------------------------------------------------------
// Kernel 5: per-row loss (exact fp32 target dot + ||w||, margin fixup)
// ---------------------------------------------------------------------------
__global__ void __launch_bounds__(256) finalize_kernel(const float* __restrict__ wt,
                                                       const void* __restrict__ lab) {
    __shared__ int s_is64;
    int tid = threadIdx.x, wid = tid >> 5, lane = tid & 31;
    if (wid == 0) {
        const int* L = (const int*)lab;
        unsigned b = __ballot_sync(0xffffffffu, L[2 * lane + 1] == 0);
        if (lane == 0) s_is64 = (b == 0xffffffffu) ? 1 : 0;
    }
    __syncthreads();
    int row = blockIdx.x * 8 + wid;
    int cls = s_is64 ? (int)((const long long*)lab)[row]
                     : ((const int*)lab)[row];

    const float4* xr = (const float4*)(g_xn + (size_t)row * DDIM);
    const float4* wp = (const float4*)(wt + (size_t)cls * DDIM);
    float4 x0 = xr[lane * 2], x1 = xr[lane * 2 + 1];
    float4 w0 = wp[lane * 2], w1 = wp[lane * 2 + 1];
    float d = x0.x*w0.x + x0.y*w0.y + x0.z*w0.z + x0.w*w0.w
            + x1.x*w1.x + x1.y*w1.y + x1.z*w1.z + x1.w*w1.w;
    float q = w0.x*w0.x + w0.y*w0.y + w0.z*w0.z + w0.w*w0.w
            + w1.x*w1.x + w1.y*w1.y + w1.z*w1.z + w1.w*w1.w;
    #pragma unroll
    for (int o = 16; o; o >>= 1) {
        d += __shfl_xor_sync(0xffffffffu, d, o);
        q += __shfl_xor_sync(0xffffffffu, q, o);
    }
    if (lane == 0) {
        float s = g_rowsum[row];
        float cosv = d * (1.f / fmaxf(sqrtf(q), 1e-12f));
        float sine = sqrtf(fminf(fmaxf(1.f - cosv * cosv, 0.f), 1.f));
        float phi = cosv * K_COS_M - sine * K_SIN_M;
        if (!(cosv - K_TH > 0.f)) phi = cosv - K_MM;
        // swap (approx) target cos term for the exact phi term
        float S = s - expf(50.f * cosv - 50.f) + expf(50.f * phi - 50.f);
        g_lossb[row] = (logf(S) + 50.f) - 50.f * phi;   // logz - target_logit
    }
}

// ---------------------------------------------------------------------------
// Kernel 6: mean over 1024 rows
// ---------------------------------------------------------------------------
__global__ void __launch_bounds__(512) reduce_kernel(float* __restrict__ out) {
    __shared__ float sm[16];
    int tid = threadIdx.x, wid = tid >> 5, lane = tid & 31;
    float v = g_lossb[tid] + g_lossb[tid + 512];
    #pragma unroll
    for (int o = 16; o; o >>= 1) v += __shfl_xor_sync(0xffffffffu, v, o);
    if (lane == 0) sm[wid] = v;
    __syncthreads();
    if (wid == 0) {
        float t = (lane < 16) ? sm[lane] : 0.f;
        #pragma unroll
        for (int o = 8; o; o >>= 1) t += __shfl_xor_sync(0xffffffffu, t, o);
        if (lane == 0) out[0] = t * (1.f / (float)B_ROWS);
    }
}

// ---------------------------------------------------------------------------
extern "C" void kernel_launch(void* const* d_in, const int* in_sizes, int n_in,
                              void* d_out, int out_size) {
    const float* x  = (const float*)d_in[0];
    const float* wt = (const float*)d_in[1];
    const void*  lb = d_in[2];
    float* out = (float*)d_out;

    cudaFuncSetAttribute(gemm_kernel, cudaFuncAttributeMaxDynamicSharedMemorySize,
                         SMEM_TOTAL);

    prep_kernel<<<B_ROWS / 8, 256>>>(x);
    wconv_kernel<<<CCLS / 8, 256>>>(wt);
    gemm_kernel<<<dim3(NTN, 8), 256, SMEM_TOTAL>>>();
    rowsum_kernel<<<B_ROWS / 256, 256>>>();
    finalize_kernel<<<B_ROWS / 8, 256>>>(wt, lb);
    reduce_kernel<<<1, 512>>>(out);
}

// round 5
// speedup vs baseline: 1.6888x; 1.0503x over previous
#include <cuda_runtime.h>
#include <cuda_bf16.h>
#include <cstdint>
#include <cstddef>

// ---------------------------------------------------------------------------
// AAM-softmax loss, sm_100-safe (plain-PTX subset: cp.async/ldmatrix/mma.sync).
//   x[1024,256] f32, weight[100000,256] f32, label[1024] (i64/i32) -> f32 loss
//
//   1) prep_kernel:   g_xn = normalize(x) fp32, g_xb = bf16 copy   (GEMM A)
//   2) wconv_kernel:  g_wb = bf16(normalize(w))                    (GEMM B)
//   3) gemm_kernel:   bf16 mma.sync 128x128xK256, occ=2, fused exp row sums
//                     -> g_part[tile][row]
//   4) rowsum_kernel: split reduction over 782 tiles -> g_rs2[8][row]
//   5) finalize_kernel: merge partials + exact fp32 target dot + margin fixup
//   6) reduce_kernel: mean -> d_out[0]
// ---------------------------------------------------------------------------

#define B_ROWS 1024
#define DDIM   256
#define CCLS   100000
#define BM 128
#define BN 128
#define BK 64
#define NKS 4                    // 256 / 64
#define NTN 782                  // ceil(100000/128)
#define RS_CH 98                 // rowsum chunk: 8*98 >= 782
#define STAGE 32768              // A 16KB + B 16KB
#define SA_OFF 0
#define SB_OFF 16384
#define NSTG 3
#define SMEM_TOTAL (NSTG * STAGE)   // 98304 -> 2 CTAs/SM

#define K_COS_M 0.9950041652780258f
#define K_SIN_M 0.09983341664682815f
#define K_TH   (-0.9950041652780258f)
#define K_MM    0.009983341664682815f

__device__ float          g_xn[B_ROWS * DDIM];
__device__ __nv_bfloat16  g_xb[B_ROWS * DDIM];
__device__ __nv_bfloat16  g_wb[(size_t)CCLS * DDIM];
__device__ float          g_part[(size_t)NTN * B_ROWS];   // [tile][row]
__device__ float          g_rs2[8 * B_ROWS];
__device__ float          g_lossb[B_ROWS];

// ---------------------------------------------------------------------------
__device__ __forceinline__ uint32_t smem_u32(const void* p) {
    uint32_t a;
    asm("{ .reg .u64 t; cvta.to.shared.u64 t, %1; cvt.u32.u64 %0, t; }"
        : "=r"(a) : "l"(p));
    return a;
}

__device__ __forceinline__ uint32_t pack_bf2(float lo, float hi) {
    __nv_bfloat162 h = __float22bfloat162_rn(make_float2(lo, hi));
    return *reinterpret_cast<uint32_t*>(&h);
}

#define CP_ASYNC16(sm, g) \
    asm volatile("cp.async.cg.shared.global [%0], [%1], 16;" :: "r"(sm), "l"(g))
#define CP_COMMIT() asm volatile("cp.async.commit_group;" ::: "memory")

#define LDSM_X4(r0, r1, r2, r3, addr) \
    asm volatile("ldmatrix.sync.aligned.m8n8.x4.shared.b16 {%0,%1,%2,%3}, [%4];" \
                 : "=r"(r0), "=r"(r1), "=r"(r2), "=r"(r3) : "r"(addr))

#define MMA_BF16(c, a, b0, b1) \
    asm volatile("mma.sync.aligned.m16n8k16.row.col.f32.bf16.bf16.f32 " \
                 "{%0,%1,%2,%3}, {%4,%5,%6,%7}, {%8,%9}, {%0,%1,%2,%3};" \
                 : "+f"((c)[0]), "+f"((c)[1]), "+f"((c)[2]), "+f"((c)[3]) \
                 : "r"((a)[0]), "r"((a)[1]), "r"((a)[2]), "r"((a)[3]), \
                   "r"(b0), "r"(b1))

// ---------------------------------------------------------------------------
// Kernel 1: normalize x rows -> fp32 + bf16 copies
// ---------------------------------------------------------------------------
__global__ void __launch_bounds__(256) prep_kernel(const float* __restrict__ x) {
    int gw = (blockIdx.x * blockDim.x + threadIdx.x) >> 5;
    int lane = threadIdx.x & 31;
    if (gw >= B_ROWS) return;
    const float4* xv = (const float4*)(x + (size_t)gw * DDIM);
    float4 a0 = xv[lane * 2], a1 = xv[lane * 2 + 1];
    float ss = a0.x*a0.x + a0.y*a0.y + a0.z*a0.z + a0.w*a0.w
             + a1.x*a1.x + a1.y*a1.y + a1.z*a1.z + a1.w*a1.w;
    #pragma unroll
    for (int o = 16; o; o >>= 1) ss += __shfl_xor_sync(0xffffffffu, ss, o);
    float inv = 1.f / fmaxf(sqrtf(ss), 1e-12f);
    a0.x *= inv; a0.y *= inv; a0.z *= inv; a0.w *= inv;
    a1.x *= inv; a1.y *= inv; a1.z *= inv; a1.w *= inv;
    ((float4*)(g_xn + (size_t)gw * DDIM))[lane * 2]     = a0;
    ((float4*)(g_xn + (size_t)gw * DDIM))[lane * 2 + 1] = a1;
    uint4 pk;
    pk.x = pack_bf2(a0.x, a0.y); pk.y = pack_bf2(a0.z, a0.w);
    pk.z = pack_bf2(a1.x, a1.y); pk.w = pack_bf2(a1.z, a1.w);
    *(uint4*)(g_xb + (size_t)gw * DDIM + lane * 8) = pk;
}

// ---------------------------------------------------------------------------
// Kernel 2: normalized bf16 weights
// ---------------------------------------------------------------------------
__global__ void __launch_bounds__(256) wconv_kernel(const float* __restrict__ wt) {
    int gw = (blockIdx.x * blockDim.x + threadIdx.x) >> 5;
    int lane = threadIdx.x & 31;
    if (gw >= CCLS) return;
    const float4* wv = (const float4*)(wt + (size_t)gw * DDIM);
    float4 a0 = wv[lane * 2], a1 = wv[lane * 2 + 1];
    float ss = a0.x*a0.x + a0.y*a0.y + a0.z*a0.z + a0.w*a0.w
             + a1.x*a1.x + a1.y*a1.y + a1.z*a1.z + a1.w*a1.w;
    #pragma unroll
    for (int o = 16; o; o >>= 1) ss += __shfl_xor_sync(0xffffffffu, ss, o);
    float inv = 1.f / fmaxf(sqrtf(ss), 1e-12f);
    uint4 pk;
    pk.x = pack_bf2(a0.x * inv, a0.y * inv); pk.y = pack_bf2(a0.z * inv, a0.w * inv);
    pk.z = pack_bf2(a1.x * inv, a1.y * inv); pk.w = pack_bf2(a1.z * inv, a1.w * inv);
    *(uint4*)(g_wb + (size_t)gw * DDIM + lane * 8) = pk;
}

// ---------------------------------------------------------------------------
// Kernel 3: bf16 mma.sync GEMM + fused exp-sum epilogue (2 CTAs/SM)
//   grid = (782, 8): x = 128-class tile, y = 128-row tile.
//   8 warps as 2x4 grid of 64x32 warp tiles. 3-stage ring over 4 K-chunks.
// ---------------------------------------------------------------------------
__global__ void __launch_bounds__(256, 2) gemm_kernel() {
    extern __shared__ __align__(1024) char smem[];
    const uint32_t sb = smem_u32(smem);
    const int tid = threadIdx.x;
    const int wid = tid >> 5, lane = tid & 31;
    const int wr = wid >> 2, wc = wid & 3;   // warp row (0..1), col (0..3)
    const int tn = blockIdx.x, tm = blockIdx.y;
    const int climit = CCLS - tn * BN;

    const int lr = lane & 7, lg = lane >> 3;
    const int kb = lg >> 1;
    const uint32_t arow = (uint32_t)(wr * 64 + (lg & 1) * 8 + lr) * 128;
    const uint32_t brow = (uint32_t)(wc * 32 + (lg & 1) * 8 + lr) * 128;

    float acc[4][4][4];
    #pragma unroll
    for (int mt = 0; mt < 4; mt++)
        #pragma unroll
        for (int nt = 0; nt < 4; nt++)
            #pragma unroll
            for (int r = 0; r < 4; r++) acc[mt][nt][r] = 0.f;

    const __nv_bfloat16* ab = g_xb + (size_t)(tm * BM) * DDIM;
    const __nv_bfloat16* bb = g_wb + (size_t)(tn * BN) * DDIM;

    auto load_stage = [&](int kk, int stg) {
        uint32_t st = sb + (uint32_t)stg * STAGE;
        #pragma unroll
        for (int i = 0; i < 4; i++) {
            int u = i * 256 + tid;
            int r = u >> 3, c8 = u & 7;
            uint32_t so = st + SA_OFF + (uint32_t)r * 128 + (uint32_t)((c8 ^ (r & 7)) << 4);
            CP_ASYNC16(so, ab + (size_t)r * DDIM + kk * BK + c8 * 8);
        }
        #pragma unroll
        for (int i = 0; i < 4; i++) {
            int u = i * 256 + tid;
            int r = u >> 3, c8 = u & 7;
            if (r < climit) {
                uint32_t so = st + SB_OFF + (uint32_t)r * 128 + (uint32_t)((c8 ^ (r & 7)) << 4);
                CP_ASYNC16(so, bb + (size_t)r * DDIM + kk * BK + c8 * 8);
            }
        }
    };

    load_stage(0, 0); CP_COMMIT();
    load_stage(1, 1); CP_COMMIT();
    load_stage(2, 2); CP_COMMIT();

    #pragma unroll
    for (int k = 0; k < NKS; k++) {
        if (k == 0)      asm volatile("cp.async.wait_group 2;" ::: "memory");
        else if (k == 1) asm volatile("cp.async.wait_group 2;" ::: "memory");
        else if (k == 2) asm volatile("cp.async.wait_group 1;" ::: "memory");
        else             asm volatile("cp.async.wait_group 0;" ::: "memory");
        __syncthreads();

        const uint32_t stb = sb + (uint32_t)(k % NSTG) * STAGE;
        const uint32_t abase = stb + SA_OFF + arow;
        const uint32_t bbase = stb + SB_OFF + brow;
        #pragma unroll
        for (int ks = 0; ks < 4; ks++) {
            const uint32_t cx = (uint32_t)(((ks * 2 + kb) ^ lr) << 4);
            uint32_t af[4][4];
            #pragma unroll
            for (int mt = 0; mt < 4; mt++)
                LDSM_X4(af[mt][0], af[mt][1], af[mt][2], af[mt][3],
                        abase + (uint32_t)mt * 2048 + cx);
            uint32_t bf[2][4];
            #pragma unroll
            for (int p = 0; p < 2; p++)
                LDSM_X4(bf[p][0], bf[p][1], bf[p][2], bf[p][3],
                        bbase + (uint32_t)p * 2048 + cx);
            #pragma unroll
            for (int mt = 0; mt < 4; mt++)
                #pragma unroll
                for (int nt = 0; nt < 4; nt++) {
                    int p = nt >> 1;
                    if (nt & 1) MMA_BF16(acc[mt][nt], af[mt], bf[p][1], bf[p][3]);
                    else        MMA_BF16(acc[mt][nt], af[mt], bf[p][2], bf[p][2]);
                }
        }
        if (k == 0) {   // recycle stage 0 for chunk 3
            __syncthreads();
            load_stage(3, 0); CP_COMMIT();
        }
    }

    // ---- epilogue: exp(50c-50) row sums (weights pre-normalized) ----
    float* rp = (float*)smem;                // [128][4] warp-col partials
    int vmax = climit < BN ? climit : BN;
    #pragma unroll
    for (int mt = 0; mt < 4; mt++) {
        #pragma unroll
        for (int h = 0; h < 2; h++) {
            float s = 0.f;
            #pragma unroll
            for (int nt = 0; nt < 4; nt++) {
                int n0 = wc * 32 + nt * 8 + (lane & 3) * 2;
                float e0 = __expf(fmaf(50.f, acc[mt][nt][h * 2],     -50.f));
                float e1 = __expf(fmaf(50.f, acc[mt][nt][h * 2 + 1], -50.f));
                s += (n0     < vmax ? e0 : 0.f);
                s += (n0 + 1 < vmax ? e1 : 0.f);
            }
            s += __shfl_xor_sync(0xffffffffu, s, 1);
            s += __shfl_xor_sync(0xffffffffu, s, 2);
            if ((lane & 3) == 0)
                rp[(wr * 64 + mt * 16 + h * 8 + (lane >> 2)) * 4 + wc] = s;
        }
    }
    __syncthreads();
    if (tid < BM) {
        float t = (rp[tid * 4] + rp[tid * 4 + 1]) + (rp[tid * 4 + 2] + rp[tid * 4 + 3]);
        g_part[(size_t)tn * B_ROWS + tm * BM + tid] = t;
    }
}

// ---------------------------------------------------------------------------
// Kernel 4: split row sums over 782 tiles -> 8 partials per row
// ---------------------------------------------------------------------------
__global__ void __launch_bounds__(256) rowsum_kernel() {
    int row = blockIdx.x * 256 + threadIdx.x;
    int t0 = blockIdx.y * RS_CH;
    int t1 = t0 + RS_CH; if (t1 > NTN) t1 = NTN;
    float s0 = 0.f, s1 = 0.f;
    int i = t0;
    for (; i + 2 <= t1; i += 2) {
        s0 += g_part[(size_t)(i + 0) * B_ROWS + row];
        s1 += g_part[(size_t)(i + 1) * B_ROWS + row];
    }
    for (; i < t1; i++) s0 += g_part[(size_t)i * B_ROWS + row];
    g_rs2[blockIdx.y * B_ROWS + row] = s0 + s1;
}

// ---------------------------------------------------------------------------
// Kernel 5: per-row loss (merge partials, exact fp32 target dot, margin fixup)
// ---------------------------------------------------------------------------
__global__ void __launch_bounds__(256) finalize_kernel(const float* __restrict__ wt,
                                                       const void* __restrict__ lab) {
    __shared__ int s_is64;
    int tid = threadIdx.x, wid = tid >> 5, lane = tid & 31;
    if (wid == 0) {
        const int* L = (const int*)lab;
        unsigned b = __ballot_sync(0xffffffffu, L[2 * lane + 1] == 0);
        if (lane == 0) s_is64 = (b == 0xffffffffu) ? 1 : 0;
    }
    __syncthreads();
    int row = blockIdx.x * 8 + wid;
    int cls = s_is64 ? (int)((const long long*)lab)[row]
                     : ((const int*)lab)[row];

    const float4* xr = (const float4*)(g_xn + (size_t)row * DDIM);
    const float4* wp = (const float4*)(wt + (size_t)cls * DDIM);
    float4 x0 = xr[lane * 2], x1 = xr[lane * 2 + 1];
    float4 w0 = wp[lane * 2], w1 = wp[lane * 2 + 1];
    float d = x0.x*w0.x + x0.y*w0.y + x0.z*w0.z + x0.w*w0.w
            + x1.x*w1.x + x1.y*w1.y + x1.z*w1.z + x1.w*w1.w;
    float q = w0.x*w0.x + w0.y*w0.y + w0.z*w0.z + w0.w*w0.w
            + w1.x*w1.x + w1.y*w1.y + w1.z*w1.z + w1.w*w1.w;
    float s = (lane < 8) ? g_rs2[lane * B_ROWS + row] : 0.f;
    #pragma unroll
    for (int o = 16; o; o >>= 1) {
        d += __shfl_xor_sync(0xffffffffu, d, o);
        q += __shfl_xor_sync(0xffffffffu, q, o);
        s += __shfl_xor_sync(0xffffffffu, s, o);
    }
    if (lane == 0) {
        float cosv = d * (1.f / fmaxf(sqrtf(q), 1e-12f));
        float sine = sqrtf(fminf(fmaxf(1.f - cosv * cosv, 0.f), 1.f));
        float phi = cosv * K_COS_M - sine * K_SIN_M;
        if (!(cosv - K_TH > 0.f)) phi = cosv - K_MM;
        float S = s - expf(50.f * cosv - 50.f) + expf(50.f * phi - 50.f);
        g_lossb[row] = (logf(S) + 50.f) - 50.f * phi;   // logz - target_logit
    }
}

// ---------------------------------------------------------------------------
// Kernel 6: mean over 1024 rows
// ---------------------------------------------------------------------------
__global__ void __launch_bounds__(512) reduce_kernel(float* __restrict__ out) {
    __shared__ float sm[16];
    int tid = threadIdx.x, wid = tid >> 5, lane = tid & 31;
    float v = g_lossb[tid] + g_lossb[tid + 512];
    #pragma unroll
    for (int o = 16; o; o >>= 1) v += __shfl_xor_sync(0xffffffffu, v, o);
    if (lane == 0) sm[wid] = v;
    __syncthreads();
    if (wid == 0) {
        float t = (lane < 16) ? sm[lane] : 0.f;
        #pragma unroll
        for (int o = 8; o; o >>= 1) t += __shfl_xor_sync(0xffffffffu, t, o);
        if (lane == 0) out[0] = t * (1.f / (float)B_ROWS);
    }
}

// ---------------------------------------------------------------------------
extern "C" void kernel_launch(void* const* d_in, const int* in_sizes, int n_in,
                              void* d_out, int out_size) {
    const float* x  = (const float*)d_in[0];
    const float* wt = (const float*)d_in[1];
    const void*  lb = d_in[2];
    float* out = (float*)d_out;

    cudaFuncSetAttribute(gemm_kernel, cudaFuncAttributeMaxDynamicSharedMemorySize,
                         SMEM_TOTAL);

    prep_kernel<<<B_ROWS / 8, 256>>>(x);
    wconv_kernel<<<CCLS / 8, 256>>>(wt);
    gemm_kernel<<<dim3(NTN, 8), 256, SMEM_TOTAL>>>();
    rowsum_kernel<<<dim3(B_ROWS / 256, 8), 256>>>();
    finalize_kernel<<<B_ROWS / 8, 256>>>(wt, lb);
    reduce_kernel<<<1, 512>>>(out);
}

// round 6
// speedup vs baseline: 2.2648x; 1.3411x over previous
#include <cuda_runtime.h>
#include <cuda_bf16.h>
#include <cstdint>
#include <cstddef>

// ---------------------------------------------------------------------------
// AAM-softmax loss, sm_100-safe (plain-PTX subset: cp.async/ldmatrix/mma.sync).
//   x[1024,256] f32, weight[100000,256] f32, label[1024] (i64/i32) -> f32 loss
//
//   1) prep_kernel:   g_xn = normalize(x) fp32; per-row int8 quant -> g_xq, g_isa
//   2) wconv_kernel:  per-class int8 quant of normalize(w) -> g_wq, g_isb
//   3) gemm_kernel:   s8 mma.sync 128x128xK256 (s32 exact accum), dequant +
//                     fused exp(50c-50) row sums -> g_part[tile][row]
//   4) rowsum_kernel: split reduction over 782 tiles -> g_rs2[32][row]
//   5) finalize_kernel: merge partials + exact fp32 target dot + margin fixup
//   6) reduce_kernel: mean -> d_out[0]
// ---------------------------------------------------------------------------

#define B_ROWS 1024
#define DDIM   256
#define CCLS   100000
#define BM 128
#define BN 128
#define BK 128                   // int8: 128 elems = 128B rows
#define NKS 2                    // 256 / 128
#define NTN 782                  // ceil(100000/128)
#define NSPLIT 32
#define RS_CH 25                 // 32*25 >= 782
#define STAGE 32768              // A 16KB + B 16KB
#define SA_OFF 0
#define SB_OFF 16384
#define SMEM_TOTAL (NKS * STAGE) // 65536 -> 2 CTAs/SM (reg-capped)

#define K_COS_M 0.9950041652780258f
#define K_SIN_M 0.09983341664682815f
#define K_TH   (-0.9950041652780258f)
#define K_MM    0.009983341664682815f

__device__ float   g_xn[B_ROWS * DDIM];
__device__ char    g_xq[B_ROWS * DDIM];
__device__ char    g_wq[(size_t)CCLS * DDIM];
__device__ float   g_isa[B_ROWS];
__device__ float   g_isb[CCLS];
__device__ float   g_part[(size_t)NTN * B_ROWS];   // [tile][row]
__device__ float   g_rs2[NSPLIT * B_ROWS];
__device__ float   g_lossb[B_ROWS];

// ---------------------------------------------------------------------------
__device__ __forceinline__ uint32_t smem_u32(const void* p) {
    uint32_t a;
    asm("{ .reg .u64 t; cvta.to.shared.u64 t, %1; cvt.u32.u64 %0, t; }"
        : "=r"(a) : "l"(p));
    return a;
}

__device__ __forceinline__ int q8(float v, float s) {
    int q = __float2int_rn(v * s);
    return q < -127 ? -127 : (q > 127 ? 127 : q);
}

#define CP_ASYNC16(sm, g) \
    asm volatile("cp.async.cg.shared.global [%0], [%1], 16;" :: "r"(sm), "l"(g))
#define CP_COMMIT() asm volatile("cp.async.commit_group;" ::: "memory")

#define LDSM_X4(r0, r1, r2, r3, addr) \
    asm volatile("ldmatrix.sync.aligned.m8n8.x4.shared.b16 {%0,%1,%2,%3}, [%4];" \
                 : "=r"(r0), "=r"(r1), "=r"(r2), "=r"(r3) : "r"(addr))

#define MMA_S8(c, a, b0, b1) \
    asm volatile("mma.sync.aligned.m16n8k32.row.col.s32.s8.s8.s32 " \
                 "{%0,%1,%2,%3}, {%4,%5,%6,%7}, {%8,%9}, {%0,%1,%2,%3};" \
                 : "+r"((c)[0]), "+r"((c)[1]), "+r"((c)[2]), "+r"((c)[3]) \
                 : "r"((a)[0]), "r"((a)[1]), "r"((a)[2]), "r"((a)[3]), \
                   "r"(b0), "r"(b1))

// ---------------------------------------------------------------------------
// Kernel 1: normalize x rows -> fp32 copy + per-row int8 quantization
// ---------------------------------------------------------------------------
__global__ void __launch_bounds__(256) prep_kernel(const float* __restrict__ x) {
    int gw = (blockIdx.x * blockDim.x + threadIdx.x) >> 5;
    int lane = threadIdx.x & 31;
    if (gw >= B_ROWS) return;
    const float4* xv = (const float4*)(x + (size_t)gw * DDIM);
    float4 a0 = xv[lane * 2], a1 = xv[lane * 2 + 1];
    float ss = a0.x*a0.x + a0.y*a0.y + a0.z*a0.z + a0.w*a0.w
             + a1.x*a1.x + a1.y*a1.y + a1.z*a1.z + a1.w*a1.w;
    #pragma unroll
    for (int o = 16; o; o >>= 1) ss += __shfl_xor_sync(0xffffffffu, ss, o);
    float inv = 1.f / fmaxf(sqrtf(ss), 1e-12f);
    a0.x *= inv; a0.y *= inv; a0.z *= inv; a0.w *= inv;
    a1.x *= inv; a1.y *= inv; a1.z *= inv; a1.w *= inv;
    ((float4*)(g_xn + (size_t)gw * DDIM))[lane * 2]     = a0;
    ((float4*)(g_xn + (size_t)gw * DDIM))[lane * 2 + 1] = a1;
    float mx = fmaxf(fmaxf(fmaxf(fabsf(a0.x), fabsf(a0.y)), fmaxf(fabsf(a0.z), fabsf(a0.w))),
                     fmaxf(fmaxf(fabsf(a1.x), fabsf(a1.y)), fmaxf(fabsf(a1.z), fabsf(a1.w))));
    #pragma unroll
    for (int o = 16; o; o >>= 1) mx = fmaxf(mx, __shfl_xor_sync(0xffffffffu, mx, o));
    mx = fmaxf(mx, 1e-12f);
    float sc = 127.f / mx;
    if (lane == 0) g_isa[gw] = mx * (1.f / 127.f);
    uint2 pk;
    pk.x = (uint32_t)(q8(a0.x,sc)&255) | ((uint32_t)(q8(a0.y,sc)&255)<<8)
         | ((uint32_t)(q8(a0.z,sc)&255)<<16) | ((uint32_t)(q8(a0.w,sc)&255)<<24);
    pk.y = (uint32_t)(q8(a1.x,sc)&255) | ((uint32_t)(q8(a1.y,sc)&255)<<8)
         | ((uint32_t)(q8(a1.z,sc)&255)<<16) | ((uint32_t)(q8(a1.w,sc)&255)<<24);
    ((uint2*)(g_xq + (size_t)gw * DDIM))[lane] = pk;
}

// ---------------------------------------------------------------------------
// Kernel 2: per-class int8 quantization of normalized weights
// ---------------------------------------------------------------------------
__global__ void __launch_bounds__(256) wconv_kernel(const float* __restrict__ wt) {
    int gw = (blockIdx.x * blockDim.x + threadIdx.x) >> 5;
    int lane = threadIdx.x & 31;
    if (gw >= CCLS) return;
    const float4* wv = (const float4*)(wt + (size_t)gw * DDIM);
    float4 a0 = wv[lane * 2], a1 = wv[lane * 2 + 1];
    float ss = a0.x*a0.x + a0.y*a0.y + a0.z*a0.z + a0.w*a0.w
             + a1.x*a1.x + a1.y*a1.y + a1.z*a1.z + a1.w*a1.w;
    #pragma unroll
    for (int o = 16; o; o >>= 1) ss += __shfl_xor_sync(0xffffffffu, ss, o);
    float inv = 1.f / fmaxf(sqrtf(ss), 1e-12f);
    a0.x *= inv; a0.y *= inv; a0.z *= inv; a0.w *= inv;
    a1.x *= inv; a1.y *= inv; a1.z *= inv; a1.w *= inv;
    float mx = fmaxf(fmaxf(fmaxf(fabsf(a0.x), fabsf(a0.y)), fmaxf(fabsf(a0.z), fabsf(a0.w))),
                     fmaxf(fmaxf(fabsf(a1.x), fabsf(a1.y)), fmaxf(fabsf(a1.z), fabsf(a1.w))));
    #pragma unroll
    for (int o = 16; o; o >>= 1) mx = fmaxf(mx, __shfl_xor_sync(0xffffffffu, mx, o));
    mx = fmaxf(mx, 1e-12f);
    float sc = 127.f / mx;
    if (lane == 0) g_isb[gw] = mx * (1.f / 127.f);
    uint2 pk;
    pk.x = (uint32_t)(q8(a0.x,sc)&255) | ((uint32_t)(q8(a0.y,sc)&255)<<8)
         | ((uint32_t)(q8(a0.z,sc)&255)<<16) | ((uint32_t)(q8(a0.w,sc)&255)<<24);
    pk.y = (uint32_t)(q8(a1.x,sc)&255) | ((uint32_t)(q8(a1.y,sc)&255)<<8)
         | ((uint32_t)(q8(a1.z,sc)&255)<<16) | ((uint32_t)(q8(a1.w,sc)&255)<<24);
    ((uint2*)(g_wq + (size_t)gw * DDIM))[lane] = pk;
}

// ---------------------------------------------------------------------------
// Kernel 3: s8 mma.sync GEMM (exact s32 accum) + dequant + exp-sum epilogue
//   grid = (782, 8): x = 128-class tile, y = 128-row tile.
//   8 warps as 2x4 grid of 64x32 warp tiles. K=256 fully prefetched (2 stages).
// ---------------------------------------------------------------------------
__global__ void __launch_bounds__(256, 2) gemm_kernel() {
    extern __shared__ __align__(1024) char smem[];
    const uint32_t sb = smem_u32(smem);
    const int tid = threadIdx.x;
    const int wid = tid >> 5, lane = tid & 31;
    const int wr = wid >> 2, wc = wid & 3;   // warp row (0..1), col (0..3)
    const int tn = blockIdx.x, tm = blockIdx.y;
    const int climit = CCLS - tn * BN;

    const int lr = lane & 7, lg = lane >> 3;
    const int kb = lg >> 1;                  // k-16B-half select
    const uint32_t arow = (uint32_t)(wr * 64 + (lg & 1) * 8 + lr) * 128;
    const uint32_t brow = (uint32_t)(wc * 32 + (lg & 1) * 8 + lr) * 128;

    int acc[4][4][4];
    #pragma unroll
    for (int mt = 0; mt < 4; mt++)
        #pragma unroll
        for (int nt = 0; nt < 4; nt++)
            #pragma unroll
            for (int r = 0; r < 4; r++) acc[mt][nt][r] = 0;

    const char* ab = g_xq + (size_t)(tm * BM) * DDIM;
    const char* bb = g_wq + (size_t)(tn * BN) * DDIM;

    auto load_stage = [&](int kk, int stg) {
        uint32_t st = sb + (uint32_t)stg * STAGE;
        #pragma unroll
        for (int i = 0; i < 4; i++) {
            int u = i * 256 + tid;
            int r = u >> 3, c8 = u & 7;
            uint32_t so = st + SA_OFF + (uint32_t)r * 128 + (uint32_t)((c8 ^ (r & 7)) << 4);
            CP_ASYNC16(so, ab + (size_t)r * DDIM + kk * BK + c8 * 16);
        }
        #pragma unroll
        for (int i = 0; i < 4; i++) {
            int u = i * 256 + tid;
            int r = u >> 3, c8 = u & 7;
            if (r < climit) {
                uint32_t so = st + SB_OFF + (uint32_t)r * 128 + (uint32_t)((c8 ^ (r & 7)) << 4);
                CP_ASYNC16(so, bb + (size_t)r * DDIM + kk * BK + c8 * 16);
            }
        }
    };

    load_stage(0, 0); CP_COMMIT();
    load_stage(1, 1); CP_COMMIT();

    #pragma unroll
    for (int k = 0; k < NKS; k++) {
        if (k == 0) asm volatile("cp.async.wait_group 1;" ::: "memory");
        else        asm volatile("cp.async.wait_group 0;" ::: "memory");
        __syncthreads();

        const uint32_t stb = sb + (uint32_t)k * STAGE;
        const uint32_t abase = stb + SA_OFF + arow;
        const uint32_t bbase = stb + SB_OFF + brow;
        #pragma unroll
        for (int ks = 0; ks < 4; ks++) {   // 4 k32 steps per 128B chunk
            const uint32_t cx = (uint32_t)(((ks * 2 + kb) ^ lr) << 4);
            uint32_t af[4][4];
            #pragma unroll
            for (int mt = 0; mt < 4; mt++)
                LDSM_X4(af[mt][0], af[mt][1], af[mt][2], af[mt][3],
                        abase + (uint32_t)mt * 2048 + cx);
            uint32_t bf[2][4];
            #pragma unroll
            for (int p = 0; p < 2; p++)
                LDSM_X4(bf[p][0], bf[p][1], bf[p][2], bf[p][3],
                        bbase + (uint32_t)p * 2048 + cx);
            // r0=(n0-7,k-lo) r1=(n8-15,k-lo) r2=(n0-7,k-hi) r3=(n8-15,k-hi)
            #pragma unroll
            for (int mt = 0; mt < 4; mt++)
                #pragma unroll
                for (int nt = 0; nt < 4; nt++) {
                    int p = nt >> 1;
                    if (nt & 1) MMA_S8(acc[mt][nt], af[mt], bf[p][1], bf[p][3]);
                    else        MMA_S8(acc[mt][nt], af[mt], bf[p][0], bf[p][2]);
                }
        }
    }
    __syncthreads();   // done with stage smem; reuse for epilogue

    // ---- epilogue: dequant, exp(50c-50), per-row partial sums ----
    float* sisa = (float*)smem;              // [128] row scales
    float* sisb = (float*)(smem + 512);      // [128] col scales
    float* rp   = (float*)(smem + 1024);     // [128][4] warp-col partials
    if (tid < BM) sisa[tid] = g_isa[tm * BM + tid];
    else if (tid < 256) {
        int c = tid - 128, cls = tn * BN + c;
        sisb[c] = (cls < CCLS) ? g_isb[cls] : 0.f;
    }
    __syncthreads();

    int vmax = climit < BN ? climit : BN;
    #pragma unroll
    for (int mt = 0; mt < 4; mt++) {
        #pragma unroll
        for (int h = 0; h < 2; h++) {
            const float isa = sisa[wr * 64 + mt * 16 + h * 8 + (lane >> 2)];
            float s = 0.f;
            #pragma unroll
            for (int nt = 0; nt < 4; nt++) {
                int n0 = wc * 32 + nt * 8 + (lane & 3) * 2;
                float c0 = (float)acc[mt][nt][h * 2]     * isa * sisb[n0];
                float c1 = (float)acc[mt][nt][h * 2 + 1] * isa * sisb[n0 + 1];
                float e0 = __expf(fmaf(50.f, c0, -50.f));
                float e1 = __expf(fmaf(50.f, c1, -50.f));
                s += (n0     < vmax ? e0 : 0.f);
                s += (n0 + 1 < vmax ? e1 : 0.f);
            }
            s += __shfl_xor_sync(0xffffffffu, s, 1);
            s += __shfl_xor_sync(0xffffffffu, s, 2);
            if ((lane & 3) == 0)
                rp[(wr * 64 + mt * 16 + h * 8 + (lane >> 2)) * 4 + wc] = s;
        }
    }
    __syncthreads();
    if (tid < BM) {
        float t = (rp[tid * 4] + rp[tid * 4 + 1]) + (rp[tid * 4 + 2] + rp[tid * 4 + 3]);
        g_part[(size_t)tn * B_ROWS + tm * BM + tid] = t;
    }
}

// ---------------------------------------------------------------------------
// Kernel 4: split row sums over 782 tiles -> 32 partials per row
// ---------------------------------------------------------------------------
__global__ void __launch_bounds__(256) rowsum_kernel() {
    int row = blockIdx.x * 256 + threadIdx.x;
    int t0 = blockIdx.y * RS_CH;
    int t1 = t0 + RS_CH; if (t1 > NTN) t1 = NTN;
    float s0 = 0.f, s1 = 0.f;
    int i = t0;
    for (; i + 2 <= t1; i += 2) {
        s0 += g_part[(size_t)(i + 0) * B_ROWS + row];
        s1 += g_part[(size_t)(i + 1) * B_ROWS + row];
    }
    for (; i < t1; i++) s0 += g_part[(size_t)i * B_ROWS + row];
    g_rs2[blockIdx.y * B_ROWS + row] = s0 + s1;
}

// ---------------------------------------------------------------------------
// Kernel 5: per-row loss (merge partials, exact fp32 target dot, margin fixup)
// ---------------------------------------------------------------------------
__global__ void __launch_bounds__(256) finalize_kernel(const float* __restrict__ wt,
                                                       const void* __restrict__ lab) {
    __shared__ int s_is64;
    int tid = threadIdx.x, wid = tid >> 5, lane = tid & 31;
    if (wid == 0) {
        const int* L = (const int*)lab;
        unsigned b = __ballot_sync(0xffffffffu, L[2 * lane + 1] == 0);
        if (lane == 0) s_is64 = (b == 0xffffffffu) ? 1 : 0;
    }
    __syncthreads();
    int row = blockIdx.x * 8 + wid;
    int cls = s_is64 ? (int)((const long long*)lab)[row]
                     : ((const int*)lab)[row];

    const float4* xr = (const float4*)(g_xn + (size_t)row * DDIM);
    const float4* wp = (const float4*)(wt + (size_t)cls * DDIM);
    float4 x0 = xr[lane * 2], x1 = xr[lane * 2 + 1];
    float4 w0 = wp[lane * 2], w1 = wp[lane * 2 + 1];
    float d = x0.x*w0.x + x0.y*w0.y + x0.z*w0.z + x0.w*w0.w
            + x1.x*w1.x + x1.y*w1.y + x1.z*w1.z + x1.w*w1.w;
    float q = w0.x*w0.x + w0.y*w0.y + w0.z*w0.z + w0.w*w0.w
            + w1.x*w1.x + w1.y*w1.y + w1.z*w1.z + w1.w*w1.w;
    float s = g_rs2[lane * B_ROWS + row];   // all 32 partials
    #pragma unroll
    for (int o = 16; o; o >>= 1) {
        d += __shfl_xor_sync(0xffffffffu, d, o);
        q += __shfl_xor_sync(0xffffffffu, q, o);
        s += __shfl_xor_sync(0xffffffffu, s, o);
    }
    if (lane == 0) {
        float cosv = d * (1.f / fmaxf(sqrtf(q), 1e-12f));
        float sine = sqrtf(fminf(fmaxf(1.f - cosv * cosv, 0.f), 1.f));
        float phi = cosv * K_COS_M - sine * K_SIN_M;
        if (!(cosv - K_TH > 0.f)) phi = cosv - K_MM;
        float S = s - expf(50.f * cosv - 50.f) + expf(50.f * phi - 50.f);
        g_lossb[row] = (logf(S) + 50.f) - 50.f * phi;   // logz - target_logit
    }
}

// ---------------------------------------------------------------------------
// Kernel 6: mean over 1024 rows
// ---------------------------------------------------------------------------
__global__ void __launch_bounds__(512) reduce_kernel(float* __restrict__ out) {
    __shared__ float sm[16];
    int tid = threadIdx.x, wid = tid >> 5, lane = tid & 31;
    float v = g_lossb[tid] + g_lossb[tid + 512];
    #pragma unroll
    for (int o = 16; o; o >>= 1) v += __shfl_xor_sync(0xffffffffu, v, o);
    if (lane == 0) sm[wid] = v;
    __syncthreads();
    if (wid == 0) {
        float t = (lane < 16) ? sm[lane] : 0.f;
        #pragma unroll
        for (int o = 8; o; o >>= 1) t += __shfl_xor_sync(0xffffffffu, t, o);
        if (lane == 0) out[0] = t * (1.f / (float)B_ROWS);
    }
}

// ---------------------------------------------------------------------------
extern "C" void kernel_launch(void* const* d_in, const int* in_sizes, int n_in,
                              void* d_out, int out_size) {
    const float* x  = (const float*)d_in[0];
    const float* wt = (const float*)d_in[1];
    const void*  lb = d_in[2];
    float* out = (float*)d_out;

    cudaFuncSetAttribute(gemm_kernel, cudaFuncAttributeMaxDynamicSharedMemorySize,
                         SMEM_TOTAL);

    prep_kernel<<<B_ROWS / 8, 256>>>(x);
    wconv_kernel<<<CCLS / 8, 256>>>(wt);
    gemm_kernel<<<dim3(NTN, 8), 256, SMEM_TOTAL>>>();
    rowsum_kernel<<<dim3(B_ROWS / 256, NSPLIT), 256>>>();
    finalize_kernel<<<B_ROWS / 8, 256>>>(wt, lb);
    reduce_kernel<<<1, 512>>>(out);
}